// round 8
// baseline (speedup 1.0000x reference)
#include <cuda_runtime.h>
#include <cuda_bf16.h>
#include <stdint.h>

// ---------------------------------------------------------------------------
// KMeans 1-D, K=256, 10 Lloyd iterations, interval-partition algorithm.
// R6: ONE persistent kernel (148 blocks x 512 threads, software grid barriers)
//     replacing 28 launches. Sorted-fast-path prep (bitonic only as fallback),
//     block-0-resident center state, 2^18 buckets, volatile cross-block state.
// ---------------------------------------------------------------------------

#define NCAP   (1 << 21)
#define NB     (1 << 18)       // buckets = top 18 bits of sortable key
#define BSHIFT 14              // 32 - 18
#define KC     256
#define NCHUNK 256
#define CHUNK  1024            // NB / NCHUNK
#define GRID   148
#define TPB    512
#define FXS    16384.0f        // 2^14 fixed-point scale
#define M48    ((1ull << 48) - 1)

// -------------------- static device state (no allocations) -----------------
__device__ unsigned long long g_hist[NB];        // packed (cnt<<48)+biased-sum
__device__ unsigned int       g_bstart[NB + 1];
__device__ long long          g_bsumpref[NB + 1];
__device__ unsigned int       g_cursor[NB];
__device__ unsigned int       g_ctot[NCHUNK];
__device__ long long          g_stot[NCHUNK];
__device__ unsigned int       g_coff[NCHUNK];
__device__ long long          g_soff[NCHUNK];
__device__ unsigned int       g_skeys[NCAP];
__device__ float              g_u[KC];
__device__ int                g_uhead[KC];
// mutating cross-block state: volatile (no per-launch L1 flush inside 1 kernel)
__device__ volatile int           g_m;
__device__ volatile unsigned int  g_T[KC];
__device__ volatile unsigned int  g_belowCnt[KC];
__device__ volatile long long     g_belowSum[KC];
// grid barrier
__device__ unsigned int           g_barcnt;
__device__ volatile unsigned int  g_bargen;

// -------------------- helpers ----------------------------------------------
__device__ __forceinline__ unsigned int f2k(float f) {
    unsigned int u = __float_as_uint(f);
    return (u & 0x80000000u) ? ~u : (u | 0x80000000u);
}
__device__ __forceinline__ float k2f(unsigned int k) {
    unsigned int u = (k & 0x80000000u) ? (k & 0x7fffffffu) : ~k;
    return __uint_as_float(u);
}
__device__ __forceinline__ long long ffix(float x) {
    return llrintf(x * FXS);
}
__device__ __forceinline__ bool prefers_left(float x, float cl, float cr, int hl, int hr) {
    float dl = fabsf(x - cl), dr = fabsf(x - cr);
    if (dl < dr) return true;
    if (dl > dr) return false;
    return hl < hr;
}

// sense-reversing software grid barrier (all blocks resident: GRID==148==#SM min)
__device__ __forceinline__ void gridbar() {
    __syncthreads();
    if (threadIdx.x == 0) {
        __threadfence();
        unsigned int gen = g_bargen;
        if (atomicAdd(&g_barcnt, 1u) == gridDim.x - 1u) {
            g_barcnt = 0u;
            __threadfence();
            g_bargen = gen + 1u;
        } else {
            while (g_bargen == gen) { __nanosleep(64); }
        }
        __threadfence();
    }
    __syncthreads();
}

struct InitIdx { int idx[KC]; };

// ===========================================================================
__global__ void __launch_bounds__(TPB, 1)
k_all(const float* __restrict__ x, float* __restrict__ out, int n, InitIdx p) {
    __shared__ unsigned long long s_pair[KC];
    __shared__ float s_cent[KC];     // persistent across iterations (block 0)
    __shared__ float s_val[KC];
    __shared__ int   s_orig[KC];
    __shared__ int   s_flag[KC];
    __shared__ int   s_pos[KC];
    __shared__ float s_u[KC];        // persistent heads/values (block 0)
    __shared__ int   s_h[KC];
    __shared__ int   s_misc;
    __shared__ unsigned int s_wc[16];
    __shared__ long long    s_ws[16];

    const int t = threadIdx.x;
    const int b = blockIdx.x;
    const int lane = t & 31, wid = t >> 5;
    const int gtid = b * TPB + t;
    const int gstride = GRID * TPB;
    const int n4 = n >> 2;
    const float4* x4 = (const float4*)x;

    // ---------------- phase 0: clear histogram ----------------
    for (int i = gtid; i < NB; i += gstride) g_hist[i] = 0ull;
    gridbar();

    // ---------------- phase 1: histogram (packed u64 atomics) ----------------
    for (int i = gtid; i < n4; i += gstride) {
        float4 v = x4[i];
        float vv[4] = { v.x, v.y, v.z, v.w };
        #pragma unroll
        for (int j = 0; j < 4; j++) {
            unsigned int bk = f2k(vv[j]) >> BSHIFT;
            long long f = ffix(vv[j]);
            atomicAdd(&g_hist[bk],
                      (1ull << 48) + (unsigned long long)(unsigned int)(f + (1LL << 31)));
        }
    }
    if (gtid == 0) {
        for (int i = n4 << 2; i < n; i++) {
            unsigned int bk = f2k(x[i]) >> BSHIFT;
            long long f = ffix(x[i]);
            atomicAdd(&g_hist[bk],
                      (1ull << 48) + (unsigned long long)(unsigned int)(f + (1LL << 31)));
        }
    }
    gridbar();

    // ---------------- phase 2: per-chunk totals ----------------
    for (int ch = b; ch < NCHUNK; ch += GRID) {
        int base = ch * CHUNK;
        unsigned int c = 0; long long s = 0;
        for (int k = t; k < CHUNK; k += TPB) {
            unsigned long long v = __ldcg(&g_hist[base + k]);
            unsigned int cc = (unsigned int)(v >> 48);
            c += cc; s += (long long)(v & M48) - ((long long)cc << 31);
        }
        #pragma unroll
        for (int off = 16; off; off >>= 1) {
            c += __shfl_down_sync(0xffffffffu, c, off);
            s += __shfl_down_sync(0xffffffffu, s, off);
        }
        if (lane == 0) { s_wc[wid] = c; s_ws[wid] = s; }
        __syncthreads();
        if (t == 0) {
            c = 0; s = 0;
            for (int w = 0; w < 16; w++) { c += s_wc[w]; s += s_ws[w]; }
            g_ctot[ch] = c; g_stot[ch] = s;
        }
        __syncthreads();
    }
    gridbar();

    // ---------------- phase 3: block 0 scans 256 chunk totals ----------------
    if (b == 0) {
        long long* s_p64 = (long long*)s_pair;
        if (t < NCHUNK) { s_pos[t] = (int)g_ctot[t]; s_p64[t] = g_stot[t]; }
        __syncthreads();
        for (int off = 1; off < NCHUNK; off <<= 1) {
            int c = 0; long long s = 0;
            if (t < NCHUNK && t >= off) { c = s_pos[t - off]; s = s_p64[t - off]; }
            __syncthreads();
            if (t < NCHUNK) { s_pos[t] += c; s_p64[t] += s; }
            __syncthreads();
        }
        if (t < NCHUNK) {
            g_coff[t] = (unsigned int)s_pos[t] - g_ctot[t];   // exclusive
            g_soff[t] = s_p64[t] - g_stot[t];
        }
        if (t == NCHUNK - 1) {
            g_bstart[NB] = (unsigned int)s_pos[t];
            g_bsumpref[NB] = s_p64[t];
        }
    }
    gridbar();

    // ---------------- phase 4: per-bucket prefix + cursor init ----------------
    for (int ch = b; ch < NCHUNK; ch += GRID) {
        int base = ch * CHUNK;
        unsigned long long v0 = __ldcg(&g_hist[base + 2 * t]);
        unsigned long long v1 = __ldcg(&g_hist[base + 2 * t + 1]);
        unsigned int c0 = (unsigned int)(v0 >> 48), c1 = (unsigned int)(v1 >> 48);
        long long sm0 = (long long)(v0 & M48) - ((long long)c0 << 31);
        long long sm1 = (long long)(v1 & M48) - ((long long)c1 << 31);
        unsigned int cp = c0 + c1; long long sp = sm0 + sm1;
        // block exclusive scan over 512 thread pairs
        unsigned int cinc = cp; long long sinc = sp;
        #pragma unroll
        for (int off = 1; off < 32; off <<= 1) {
            unsigned int uc = __shfl_up_sync(0xffffffffu, cinc, off);
            long long    us = __shfl_up_sync(0xffffffffu, sinc, off);
            if (lane >= off) { cinc += uc; sinc += us; }
        }
        if (lane == 31) { s_wc[wid] = cinc; s_ws[wid] = sinc; }
        __syncthreads();
        if (wid == 0) {
            unsigned int wc = (lane < 16) ? s_wc[lane] : 0u;
            long long    ws = (lane < 16) ? s_ws[lane] : 0ll;
            #pragma unroll
            for (int off = 1; off < 16; off <<= 1) {
                unsigned int uc = __shfl_up_sync(0xffffffffu, wc, off);
                long long    us = __shfl_up_sync(0xffffffffu, ws, off);
                if (lane >= off) { wc += uc; ws += us; }
            }
            if (lane < 16) { s_wc[lane] = wc; s_ws[lane] = ws; }
        }
        __syncthreads();
        unsigned int cexc = cinc - cp + (wid ? s_wc[wid - 1] : 0u);
        long long    sexc = sinc - sp + (wid ? s_ws[wid - 1] : 0ll);
        unsigned int runc = g_coff[ch] + cexc;
        long long    runs = g_soff[ch] + sexc;
        g_bstart[base + 2 * t] = runc; g_cursor[base + 2 * t] = runc;
        g_bsumpref[base + 2 * t] = runs;
        runc += c0; runs += sm0;
        g_bstart[base + 2 * t + 1] = runc; g_cursor[base + 2 * t + 1] = runc;
        g_bsumpref[base + 2 * t + 1] = runs;
        __syncthreads();
    }
    gridbar();

    // ---------------- phase 5: scatter keys ----------------
    for (int i = gtid; i < n4; i += gstride) {
        float4 v = x4[i];
        float vv[4] = { v.x, v.y, v.z, v.w };
        #pragma unroll
        for (int j = 0; j < 4; j++) {
            unsigned int k = f2k(vv[j]);
            unsigned int slot = atomicAdd(&g_cursor[k >> BSHIFT], 1u);
            g_skeys[slot] = k;
        }
    }
    if (gtid == 0) {
        for (int i = n4 << 2; i < n; i++) {
            unsigned int k = f2k(x[i]);
            unsigned int slot = atomicAdd(&g_cursor[k >> BSHIFT], 1u);
            g_skeys[slot] = k;
        }
    }
    gridbar();

    // ---------------- iteration loop: 11 preps, 10 boundary passes ----------
    for (int it = 0; it <= 10; it++) {
        if (b == 0) {
            // -- update (or init) centers, kept resident in smem --
            if (it == 0) {
                if (t < KC) s_cent[t] = x[p.idx[t]];
            } else {
                int pm = g_m;
                if (t < pm) {
                    unsigned int c0 = t ? g_belowCnt[t - 1] : 0u;
                    unsigned int c1 = (t == pm - 1) ? (unsigned int)n : g_belowCnt[t];
                    long long ss0 = t ? g_belowSum[t - 1] : 0ll;
                    long long ss1 = (t == pm - 1) ? g_bsumpref[NB] : g_belowSum[t];
                    unsigned int cnt = c1 - c0;
                    if (cnt) {
                        double mean = ((double)(ss1 - ss0) / (double)FXS) / (double)cnt;
                        s_cent[s_h[t]] = (float)mean;
                    }
                }
            }
            __syncthreads();
            if (t < KC)
                s_pair[t] = ((unsigned long long)f2k(s_cent[t]) << 32) | (unsigned int)t;
            if (t == 0) s_misc = 0;
            __syncthreads();
            if (t < KC - 1 && s_pair[t] > s_pair[t + 1]) s_misc = 1;
            __syncthreads();
            if (s_misc) {   // fallback full bitonic sort (init + rare stale-dup case)
                for (int k = 2; k <= KC; k <<= 1) {
                    for (int j = k >> 1; j; j >>= 1) {
                        int ixj = t ^ j;
                        if (t < KC && ixj > t) {
                            unsigned long long a = s_pair[t], bb = s_pair[ixj];
                            bool up = ((t & k) == 0);
                            if (up ? (a > bb) : (a < bb)) { s_pair[t] = bb; s_pair[ixj] = a; }
                        }
                        __syncthreads();
                    }
                }
            }
            if (t < KC) {
                s_val[t]  = k2f((unsigned int)(s_pair[t] >> 32));
                s_orig[t] = (int)(s_pair[t] & 0xffffffffu);
            }
            __syncthreads();
            if (t < KC) s_flag[t] = (t == 0) || (s_val[t] != s_val[t - 1]);
            __syncthreads();
            if (t < KC) s_pos[t] = s_flag[t];
            __syncthreads();
            for (int off = 1; off < KC; off <<= 1) {
                int v = 0;
                if (t < KC && t >= off) v = s_pos[t - off];
                __syncthreads();
                if (t < KC) s_pos[t] += v;
                __syncthreads();
            }
            int m = s_pos[KC - 1];
            if (t < KC && s_flag[t]) {
                int d = s_pos[t] - 1;
                int mn = s_orig[t];
                for (int q = t + 1; q < KC && !s_flag[q]; q++) mn = min(mn, s_orig[q]);
                s_u[d] = s_val[t]; s_h[d] = mn;
                g_u[d] = s_val[t]; g_uhead[d] = mn;
            }
            if (t == 0) g_m = m;
            __syncthreads();
            if (t < m - 1) {     // exact flip-point per adjacent pair
                float cl = s_u[t], cr = s_u[t + 1];
                int   hl = s_h[t], hr = s_h[t + 1];
                unsigned int lo = f2k(cl), hi = f2k(cr);
                while (hi - lo > 1u) {
                    unsigned int mid = lo + ((hi - lo) >> 1);
                    if (prefers_left(k2f(mid), cl, cr, hl, hr)) lo = mid; else hi = mid;
                }
                g_T[t] = hi;
            }
            __syncthreads();
        }
        gridbar();

        if (it < 10) {
            int m = g_m;
            for (int j = b; j < m - 1; j += GRID) {
                unsigned int T = g_T[j];
                unsigned int bk = T >> BSHIFT;
                unsigned int st = g_bstart[bk], en = g_bstart[bk + 1];
                unsigned int c = 0; long long s = 0;
                for (unsigned int i = st + t; i < en; i += TPB) {
                    unsigned int k = g_skeys[i];
                    if (k < T) { c++; s += ffix(k2f(k)); }
                }
                #pragma unroll
                for (int off = 16; off; off >>= 1) {
                    c += __shfl_down_sync(0xffffffffu, c, off);
                    s += __shfl_down_sync(0xffffffffu, s, off);
                }
                if (lane == 0) { s_wc[wid] = c; s_ws[wid] = s; }
                __syncthreads();
                if (t == 0) {
                    c = 0; s = 0;
                    for (int w = 0; w < 16; w++) { c += s_wc[w]; s += s_ws[w]; }
                    g_belowCnt[j] = st + c;
                    g_belowSum[j] = g_bsumpref[bk] + s;
                }
                __syncthreads();
            }
            gridbar();
        }
    }

    // ---------------- final remap ----------------
    {
        int m = g_m;
        if (t < KC) {
            s_u[t] = (t < m) ? g_u[t] : __int_as_float(0x7f800000);
            s_h[t] = (t < m) ? g_uhead[t] : 0x7fffffff;
        }
        __syncthreads();
        float4* o4 = (float4*)out;
        for (int i = gtid; i < n4; i += gstride) {
            float4 v = x4[i];
            float vv[4] = { v.x, v.y, v.z, v.w };
            float rr[4];
            #pragma unroll
            for (int j = 0; j < 4; j++) {
                float val = vv[j];
                int pp = 0;
                #pragma unroll
                for (int step = 128; step > 0; step >>= 1) {
                    int np = pp + step;
                    if (s_u[np - 1] < val) pp = np;
                }
                float res;
                if (pp == 0)      res = s_u[0];
                else if (pp >= m) res = s_u[m - 1];
                else {
                    float cl = s_u[pp - 1], cr = s_u[pp];
                    float dl = fabsf(val - cl), dr = fabsf(val - cr);
                    res = (dl < dr) ? cl : (dr < dl) ? cr
                        : ((s_h[pp - 1] < s_h[pp]) ? cl : cr);
                }
                rr[j] = res;
            }
            o4[i] = make_float4(rr[0], rr[1], rr[2], rr[3]);
        }
        if (gtid == 0) {
            for (int i = n4 << 2; i < n; i++) {
                float val = x[i];
                int pp = 0;
                for (int step = 128; step > 0; step >>= 1) {
                    int np = pp + step;
                    if (s_u[np - 1] < val) pp = np;
                }
                float res;
                if (pp == 0)      res = s_u[0];
                else if (pp >= m) res = s_u[m - 1];
                else {
                    float cl = s_u[pp - 1], cr = s_u[pp];
                    float dl = fabsf(val - cl), dr = fabsf(val - cr);
                    res = (dl < dr) ? cl : (dr < dl) ? cr
                        : ((s_h[pp - 1] < s_h[pp]) ? cl : cr);
                }
                out[i] = res;
            }
        }
    }
}

// -------------------- host: JAX threefry-2x32 replication -------------------
static inline uint32_t rotl32(uint32_t x, int d) { return (x << d) | (x >> (32 - d)); }
static void tf2x32(uint32_t k0, uint32_t k1, uint32_t x0, uint32_t x1,
                   uint32_t* o0, uint32_t* o1) {
    uint32_t ks[3] = { k0, k1, (uint32_t)(k0 ^ k1 ^ 0x1BD11BDAu) };
    uint32_t v0 = x0 + ks[0], v1 = x1 + ks[1];
    static const int R[2][4] = { {13, 15, 26, 6}, {17, 29, 16, 24} };
    for (int g = 0; g < 5; g++) {
        const int* r = R[g & 1];
        for (int i = 0; i < 4; i++) { v0 += v1; v1 = rotl32(v1, r[i]); v1 ^= v0; }
        v0 += ks[(g + 1) % 3];
        v1 += ks[(g + 2) % 3] + (uint32_t)(g + 1);
    }
    *o0 = v0; *o1 = v1;
}

extern "C" void kernel_launch(void* const* d_in, const int* in_sizes, int n_in,
                              void* d_out, int out_size) {
    const float* x = (const float*)d_in[0];
    float* out = (float*)d_out;
    int n = in_sizes[0];

    InitIdx p;
    {
        uint32_t span = (uint32_t)n;
        uint32_t k1a, k1b, k2a, k2b;
        tf2x32(0u, 42u, 0u, 0u, &k1a, &k1b);
        tf2x32(0u, 42u, 0u, 1u, &k2a, &k2b);
        uint32_t m1 = 65536u % span;
        uint32_t mult = ((uint32_t)(m1 * m1)) % span;
        for (int i = 0; i < KC; i++) {
            uint32_t h1, h2, l1, l2;
            tf2x32(k1a, k1b, 0u, (uint32_t)i, &h1, &h2);
            tf2x32(k2a, k2b, 0u, (uint32_t)i, &l1, &l2);
            uint32_t hb = h1 ^ h2, lb = l1 ^ l2;
            uint32_t off = ((uint32_t)((hb % span) * mult) + (lb % span)) % span;
            p.idx[i] = (int)off;
        }
    }

    k_all<<<GRID, TPB>>>(x, out, n, p);
}

// round 9
// speedup vs baseline: 1.1928x; 1.1928x over previous
#include <cuda_runtime.h>
#include <cuda_bf16.h>
#include <stdint.h>

// ---------------------------------------------------------------------------
// KMeans 1-D, K=256, 10 Lloyd iterations, interval-partition algorithm.
// R9 hybrid: fat multi-launch grids for bulk phases (R5 form), ONE persistent
//     148x256 kernel for the 11-prep/10-bnd loop with redundant per-block prep
//     (1 grid barrier per iteration). clear folded into k_out, init into loop.
// ---------------------------------------------------------------------------

#define NCAP   (1 << 21)
#define NB     (1 << 20)       // buckets = top 20 bits of sortable key
#define BSHIFT 12              // 32 - 20
#define KC     256
#define CHUNK  1024
#define SCB    (NB / CHUNK)    // 1024
#define GRIDL  148             // loop kernel grid (1 block/SM, co-resident)
#define FXS    16384.0f        // 2^14 fixed-point scale
#define M48    ((1ull << 48) - 1)

// -------------------- static device state (no allocations) -----------------
__device__ unsigned long long g_hist[NB];        // zeroed at end of each call
__device__ unsigned int       g_bstart[NB + 1];
__device__ long long          g_bsumpref[NB + 1];
__device__ unsigned int       g_cursor[NB];
__device__ unsigned int       g_ctot[SCB];
__device__ long long          g_stot[SCB];
__device__ unsigned int       g_coff[SCB];
__device__ long long          g_soff[SCB];
__device__ unsigned int       g_skeys[NCAP];
__device__ float              g_u[KC];
__device__ int                g_uhead[KC];
__device__ int                g_m;
// cross-block mutables inside the persistent loop kernel
__device__ volatile unsigned int g_belowCnt[KC];
__device__ volatile long long    g_belowSum[KC];
// grid barrier state
__device__ unsigned int          g_barcnt;
__device__ volatile unsigned int g_bargen;

// -------------------- helpers ----------------------------------------------
__device__ __forceinline__ unsigned int f2k(float f) {
    unsigned int u = __float_as_uint(f);
    return (u & 0x80000000u) ? ~u : (u | 0x80000000u);
}
__device__ __forceinline__ float k2f(unsigned int k) {
    unsigned int u = (k & 0x80000000u) ? (k & 0x7fffffffu) : ~k;
    return __uint_as_float(u);
}
__device__ __forceinline__ long long ffix(float x) {
    return llrintf(x * FXS);
}
__device__ __forceinline__ bool prefers_left(float x, float cl, float cr, int hl, int hr) {
    float dl = fabsf(x - cl), dr = fabsf(x - cr);
    if (dl < dr) return true;
    if (dl > dr) return false;
    return hl < hr;
}
__device__ __forceinline__ void gridbar() {
    __syncthreads();
    if (threadIdx.x == 0) {
        __threadfence();
        unsigned int gen = g_bargen;
        if (atomicAdd(&g_barcnt, 1u) == gridDim.x - 1u) {
            g_barcnt = 0u;
            __threadfence();
            g_bargen = gen + 1u;
        } else {
            while (g_bargen == gen) { __nanosleep(64); }
        }
        __threadfence();
    }
    __syncthreads();
}

// -------------------- hist: global packed atomics --------------------------
__global__ void __launch_bounds__(256) k_hist(const float* __restrict__ x, int n) {
    const float4* x4 = (const float4*)x;
    int n4 = n >> 2;
    int stride = gridDim.x * blockDim.x;
    for (int i = blockIdx.x * blockDim.x + threadIdx.x; i < n4; i += stride) {
        float4 v = x4[i];
        float vv[4] = { v.x, v.y, v.z, v.w };
        #pragma unroll
        for (int j = 0; j < 4; j++) {
            unsigned int b = f2k(vv[j]) >> BSHIFT;
            long long f = ffix(vv[j]);
            atomicAdd(&g_hist[b],
                      (1ull << 48) + (unsigned long long)(unsigned int)(f + (1LL << 31)));
        }
    }
    if (blockIdx.x == 0 && threadIdx.x == 0) {
        for (int i = n4 << 2; i < n; i++) {
            unsigned int b = f2k(x[i]) >> BSHIFT;
            long long f = ffix(x[i]);
            atomicAdd(&g_hist[b],
                      (1ull << 48) + (unsigned long long)(unsigned int)(f + (1LL << 31)));
        }
    }
}

// -------------------- scan A: per-chunk totals ------------------------------
__global__ void __launch_bounds__(256) k_scanA() {
    __shared__ unsigned int rc[256];
    __shared__ long long    rs[256];
    int t = threadIdx.x;
    int base = blockIdx.x * CHUNK + t * 4;
    unsigned int c = 0; long long s = 0;
    #pragma unroll
    for (int k = 0; k < 4; k++) {
        unsigned long long v = g_hist[base + k];
        unsigned int cnt = (unsigned int)(v >> 48);
        c += cnt; s += (long long)(v & M48) - ((long long)cnt << 31);
    }
    rc[t] = c; rs[t] = s;
    __syncthreads();
    for (int off = 128; off > 0; off >>= 1) {
        if (t < off) { rc[t] += rc[t + off]; rs[t] += rs[t + off]; }
        __syncthreads();
    }
    if (t == 0) { g_ctot[blockIdx.x] = rc[0]; g_stot[blockIdx.x] = rs[0]; }
}

// -------------------- scan B: scan 1024 chunk totals ------------------------
__global__ void __launch_bounds__(1024) k_scanB() {
    __shared__ unsigned int s_c[1024];
    __shared__ long long    s_s[1024];
    int t = threadIdx.x;
    unsigned int c = g_ctot[t];
    long long    s = g_stot[t];
    s_c[t] = c; s_s[t] = s;
    __syncthreads();
    for (int off = 1; off < 1024; off <<= 1) {
        unsigned int cc = (t >= off) ? s_c[t - off] : 0u;
        long long    ss = (t >= off) ? s_s[t - off] : 0ll;
        __syncthreads();
        s_c[t] += cc; s_s[t] += ss;
        __syncthreads();
    }
    g_coff[t] = s_c[t] - c;   // exclusive
    g_soff[t] = s_s[t] - s;
    if (t == 1023) { g_bstart[NB] = s_c[1023]; g_bsumpref[NB] = s_s[1023]; }
}

// -------------------- scan C: final prefix + cursor init --------------------
__global__ void __launch_bounds__(256) k_scanC() {
    __shared__ unsigned int s_c[256];
    __shared__ long long    s_s[256];
    int t = threadIdx.x;
    int base = blockIdx.x * CHUNK + t * 4;
    unsigned int cnt4[4]; long long sum4[4];
    unsigned int c = 0; long long s = 0;
    #pragma unroll
    for (int k = 0; k < 4; k++) {
        unsigned long long v = g_hist[base + k];
        cnt4[k] = (unsigned int)(v >> 48);
        sum4[k] = (long long)(v & M48) - ((long long)cnt4[k] << 31);
        c += cnt4[k]; s += sum4[k];
    }
    s_c[t] = c; s_s[t] = s;
    __syncthreads();
    for (int off = 1; off < 256; off <<= 1) {
        unsigned int cc = (t >= off) ? s_c[t - off] : 0u;
        long long    ss = (t >= off) ? s_s[t - off] : 0ll;
        __syncthreads();
        s_c[t] += cc; s_s[t] += ss;
        __syncthreads();
    }
    unsigned int runc = g_coff[blockIdx.x] + s_c[t] - c;
    long long    runs = g_soff[blockIdx.x] + s_s[t] - s;
    #pragma unroll
    for (int k = 0; k < 4; k++) {
        g_bstart[base + k]   = runc;
        g_cursor[base + k]   = runc;
        g_bsumpref[base + k] = runs;
        runc += cnt4[k]; runs += sum4[k];
    }
}

// -------------------- scatter: per-bucket global cursors --------------------
__global__ void __launch_bounds__(256) k_scatter(const float* __restrict__ x, int n) {
    const float4* x4 = (const float4*)x;
    int n4 = n >> 2;
    int stride = gridDim.x * blockDim.x;
    for (int i = blockIdx.x * blockDim.x + threadIdx.x; i < n4; i += stride) {
        float4 v = x4[i];
        float vv[4] = { v.x, v.y, v.z, v.w };
        #pragma unroll
        for (int j = 0; j < 4; j++) {
            unsigned int k = f2k(vv[j]);
            unsigned int slot = atomicAdd(&g_cursor[k >> BSHIFT], 1u);
            g_skeys[slot] = k;
        }
    }
    if (blockIdx.x == 0 && threadIdx.x == 0) {
        for (int i = n4 << 2; i < n; i++) {
            unsigned int k = f2k(x[i]);
            unsigned int slot = atomicAdd(&g_cursor[k >> BSHIFT], 1u);
            g_skeys[slot] = k;
        }
    }
}

// -------------------- persistent loop: 11 preps + 10 boundary passes --------
// Every block redundantly computes the identical prep (deterministic ops on
// identical global inputs), so only ONE grid barrier per iteration is needed
// (after bnd, before the next prep reads g_belowCnt/Sum).
struct InitIdx { int idx[KC]; };

__global__ void __launch_bounds__(KC, 1)
k_loop(const float* __restrict__ x, int n, InitIdx p) {
    __shared__ unsigned long long s_pair[KC];
    __shared__ float s_cent[KC];   // persists across iterations (per block)
    __shared__ float s_val[KC];
    __shared__ int   s_orig[KC];
    __shared__ int   s_flag[KC];
    __shared__ int   s_pos[KC];
    __shared__ float s_u[KC];
    __shared__ int   s_h[KC];
    __shared__ unsigned int s_T[KC];
    __shared__ int   s_misc;
    __shared__ int   s_m;

    const int t = threadIdx.x;
    const int b = blockIdx.x;
    const long long totsum = g_bsumpref[NB];   // stable during this kernel

    for (int it = 0; it <= 10; it++) {
        // ---- update (or init) centers ----
        if (it == 0) {
            s_cent[t] = x[p.idx[t]];
        } else {
            int pm = s_m;
            if (t < pm) {
                unsigned int c0 = t ? g_belowCnt[t - 1] : 0u;
                unsigned int c1 = (t == pm - 1) ? (unsigned int)n : g_belowCnt[t];
                long long ss0 = t ? g_belowSum[t - 1] : 0ll;
                long long ss1 = (t == pm - 1) ? totsum : g_belowSum[t];
                unsigned int cnt = c1 - c0;
                if (cnt) {
                    double mean = ((double)(ss1 - ss0) / (double)FXS) / (double)cnt;
                    s_cent[s_h[t]] = (float)mean;  // heads are distinct indices
                }
            }
        }
        __syncthreads();

        // ---- sort (fast path: already sorted) ----
        s_pair[t] = ((unsigned long long)f2k(s_cent[t]) << 32) | (unsigned int)t;
        if (t == 0) s_misc = 0;
        __syncthreads();
        if (t < KC - 1 && s_pair[t] > s_pair[t + 1]) s_misc = 1;
        __syncthreads();
        if (s_misc) {
            for (int k = 2; k <= KC; k <<= 1) {
                for (int j = k >> 1; j; j >>= 1) {
                    int ixj = t ^ j;
                    if (ixj > t) {
                        unsigned long long a = s_pair[t], bb = s_pair[ixj];
                        bool up = ((t & k) == 0);
                        if (up ? (a > bb) : (a < bb)) { s_pair[t] = bb; s_pair[ixj] = a; }
                    }
                    __syncthreads();
                }
            }
        }
        s_val[t]  = k2f((unsigned int)(s_pair[t] >> 32));
        s_orig[t] = (int)(s_pair[t] & 0xffffffffu);
        __syncthreads();

        // ---- dedupe into distinct runs ----
        s_flag[t] = (t == 0) || (s_val[t] != s_val[t - 1]);
        __syncthreads();
        s_pos[t] = s_flag[t];
        __syncthreads();
        for (int off = 1; off < KC; off <<= 1) {
            int v = (t >= off) ? s_pos[t - off] : 0;
            __syncthreads();
            s_pos[t] += v;
            __syncthreads();
        }
        int m = s_pos[KC - 1];
        if (s_flag[t]) {
            int d = s_pos[t] - 1;
            int mn = s_orig[t];
            for (int q = t + 1; q < KC && !s_flag[q]; q++) mn = min(mn, s_orig[q]);
            s_u[d] = s_val[t]; s_h[d] = mn;
        }
        if (t == 0) s_m = m;
        __syncthreads();

        // ---- exact flip-point thresholds ----
        if (t < m - 1) {
            float cl = s_u[t], cr = s_u[t + 1];
            int   hl = s_h[t], hr = s_h[t + 1];
            unsigned int lo = f2k(cl), hi = f2k(cr);
            while (hi - lo > 1u) {
                unsigned int mid = lo + ((hi - lo) >> 1);
                if (prefers_left(k2f(mid), cl, cr, hl, hr)) lo = mid; else hi = mid;
            }
            s_T[t] = hi;
        }
        __syncthreads();

        // ---- boundary residual scans (this block's thresholds only) ----
        if (it < 10) {
            for (int j = b; j < m - 1; j += GRIDL) {
                unsigned int T = s_T[j];
                unsigned int bk = T >> BSHIFT;
                unsigned int st = g_bstart[bk], en = g_bstart[bk + 1];
                unsigned int c = 0; long long s = 0;
                for (unsigned int i = st + t; i < en; i += KC) {
                    unsigned int k = g_skeys[i];
                    if (k < T) { c++; s += ffix(k2f(k)); }
                }
                // block reduce (reuse s_pos / s_pair as scratch)
                s_pos[t] = (int)c;
                ((long long*)s_pair)[t] = s;
                __syncthreads();
                for (int off = 128; off > 0; off >>= 1) {
                    if (t < off) {
                        s_pos[t] += s_pos[t + off];
                        ((long long*)s_pair)[t] += ((long long*)s_pair)[t + off];
                    }
                    __syncthreads();
                }
                if (t == 0) {
                    g_belowCnt[j] = st + (unsigned int)s_pos[0];
                    g_belowSum[j] = g_bsumpref[bk] + ((long long*)s_pair)[0];
                }
                __syncthreads();
            }
            gridbar();   // publish belowCnt/Sum for next iteration's prep
        }
    }

    // ---- export final partition for k_out ----
    if (b == 0) {
        int m = s_m;
        if (t < m) { g_u[t] = s_u[t]; g_uhead[t] = s_h[t]; }
        if (t == 0) g_m = m;
    }
}

// -------------------- final remap + hist clear for next replay --------------
__global__ void __launch_bounds__(256) k_out(const float* __restrict__ x,
                                             float* __restrict__ out, int n) {
    __shared__ float s_u[KC];
    __shared__ int   s_h[KC];
    int t = threadIdx.x;
    int m = g_m;
    s_u[t] = (t < m) ? g_u[t] : __int_as_float(0x7f800000);
    s_h[t] = (t < m) ? g_uhead[t] : 0x7fffffff;
    __syncthreads();
    const float4* x4 = (const float4*)x;
    float4* o4 = (float4*)out;
    int n4 = n >> 2;
    int stride = gridDim.x * blockDim.x;
    for (int i = blockIdx.x * blockDim.x + t; i < n4; i += stride) {
        float4 v = x4[i];
        float vv[4] = { v.x, v.y, v.z, v.w };
        float rr[4];
        #pragma unroll
        for (int j = 0; j < 4; j++) {
            float val = vv[j];
            int p = 0;
            #pragma unroll
            for (int step = 128; step > 0; step >>= 1) {
                int np = p + step;
                if (s_u[np - 1] < val) p = np;
            }
            float res;
            if (p == 0)      res = s_u[0];
            else if (p >= m) res = s_u[m - 1];
            else {
                float cl = s_u[p - 1], cr = s_u[p];
                float dl = fabsf(val - cl), dr = fabsf(val - cr);
                res = (dl < dr) ? cl : (dr < dl) ? cr : ((s_h[p - 1] < s_h[p]) ? cl : cr);
            }
            rr[j] = res;
        }
        o4[i] = make_float4(rr[0], rr[1], rr[2], rr[3]);
    }
    if (blockIdx.x == 0 && t == 0) {
        for (int i = n4 << 2; i < n; i++) {
            float val = x[i];
            int p = 0;
            for (int step = 128; step > 0; step >>= 1) {
                int np = p + step;
                if (s_u[np - 1] < val) p = np;
            }
            float res;
            if (p == 0)      res = s_u[0];
            else if (p >= m) res = s_u[m - 1];
            else {
                float cl = s_u[p - 1], cr = s_u[p];
                float dl = fabsf(val - cl), dr = fabsf(val - cr);
                res = (dl < dr) ? cl : (dr < dl) ? cr : ((s_h[p - 1] < s_h[p]) ? cl : cr);
            }
            out[i] = res;
        }
    }
    // clear histogram for the next call/replay (invariant: zero at call entry)
    for (int i = blockIdx.x * blockDim.x + t; i < NB; i += stride)
        g_hist[i] = 0ull;
}

// -------------------- host: JAX threefry-2x32 replication -------------------
static inline uint32_t rotl32(uint32_t x, int d) { return (x << d) | (x >> (32 - d)); }
static void tf2x32(uint32_t k0, uint32_t k1, uint32_t x0, uint32_t x1,
                   uint32_t* o0, uint32_t* o1) {
    uint32_t ks[3] = { k0, k1, (uint32_t)(k0 ^ k1 ^ 0x1BD11BDAu) };
    uint32_t v0 = x0 + ks[0], v1 = x1 + ks[1];
    static const int R[2][4] = { {13, 15, 26, 6}, {17, 29, 16, 24} };
    for (int g = 0; g < 5; g++) {
        const int* r = R[g & 1];
        for (int i = 0; i < 4; i++) { v0 += v1; v1 = rotl32(v1, r[i]); v1 ^= v0; }
        v0 += ks[(g + 1) % 3];
        v1 += ks[(g + 2) % 3] + (uint32_t)(g + 1);
    }
    *o0 = v0; *o1 = v1;
}

extern "C" void kernel_launch(void* const* d_in, const int* in_sizes, int n_in,
                              void* d_out, int out_size) {
    const float* x = (const float*)d_in[0];
    float* out = (float*)d_out;
    int n = in_sizes[0];

    InitIdx p;
    {
        uint32_t span = (uint32_t)n;
        uint32_t k1a, k1b, k2a, k2b;
        tf2x32(0u, 42u, 0u, 0u, &k1a, &k1b);
        tf2x32(0u, 42u, 0u, 1u, &k2a, &k2b);
        uint32_t m1 = 65536u % span;
        uint32_t mult = ((uint32_t)(m1 * m1)) % span;
        for (int i = 0; i < KC; i++) {
            uint32_t h1, h2, l1, l2;
            tf2x32(k1a, k1b, 0u, (uint32_t)i, &h1, &h2);
            tf2x32(k2a, k2b, 0u, (uint32_t)i, &l1, &l2);
            uint32_t hb = h1 ^ h2, lb = l1 ^ l2;
            uint32_t off = ((uint32_t)((hb % span) * mult) + (lb % span)) % span;
            p.idx[i] = (int)off;
        }
    }

    k_hist<<<2048, 256>>>(x, n);           // g_hist is zero at entry (invariant)
    k_scanA<<<SCB, 256>>>();
    k_scanB<<<1, 1024>>>();
    k_scanC<<<SCB, 256>>>();
    k_scatter<<<2048, 256>>>(x, n);
    k_loop<<<GRIDL, KC>>>(x, n, p);
    k_out<<<1024, 256>>>(x, out, n);
}